// round 3
// baseline (speedup 1.0000x reference)
#include <cuda_runtime.h>
#include <math.h>

#define DM   1024          // d_model
#define DS   16            // d_state
#define NB   4096          // batch
#define NBC  (DM * DS * 2) // 32768 bc columns

// ---------------- scratch (device globals; no runtime allocation) ----------
__device__ float g_u [NB * DM];   // 16 MB
__device__ float g_dt[NB * DM];   // 16 MB (softplus already applied)
__device__ float g_z [NB * DM];   // 16 MB (silu(y))
__device__ float g_An[DM * DS];   // -exp(A_log)

// ---------------- helpers --------------------------------------------------
__device__ __forceinline__ float softplus_f(float x) {
    return x > 20.f ? x : log1pf(__expf(x));
}

// ---------------- tiny prep kernel: A = -exp(A_log) ------------------------
__global__ void prep_A(const float* __restrict__ A_log) {
    int i = blockIdx.x * 256 + threadIdx.x;
    if (i < DM * DS) g_An[i] = -__expf(A_log[i]);
}

// ---------------- generic SGEMM: OUT[M,N] = A[M,K] @ W[N,K]^T --------------
// BM=BN=128, BK=8, 256 threads, 8x8 microtile.
// EPI: 0 = none, 1 = softplus(v + bias[n]), 2 = v + bias[n]
template <int EPI>
__global__ void __launch_bounds__(256, 2)
sgemm128(const float* __restrict__ A, const float* __restrict__ W,
         const float* __restrict__ bias, float* __restrict__ Out,
         int N, int K)
{
    __shared__ float As[8][128];
    __shared__ float Bs[8][128];

    const int tid = threadIdx.x;
    const int tx  = tid & 15;
    const int ty  = tid >> 4;
    const int bm  = blockIdx.y * 128;
    const int bn  = blockIdx.x * 128;

    float acc[8][8];
#pragma unroll
    for (int i = 0; i < 8; i++)
#pragma unroll
        for (int j = 0; j < 8; j++) acc[i][j] = 0.f;

    const int lr = tid >> 1;          // 0..127
    const int lc = (tid & 1) * 4;     // 0 or 4
    const float* Ap = A + (size_t)(bm + lr) * K + lc;
    const float* Wp = W + (size_t)(bn + lr) * K + lc;

    for (int kt = 0; kt < K; kt += 8) {
        float4 av = *(const float4*)(Ap + kt);
        float4 bv = *(const float4*)(Wp + kt);
        As[lc + 0][lr] = av.x; As[lc + 1][lr] = av.y;
        As[lc + 2][lr] = av.z; As[lc + 3][lr] = av.w;
        Bs[lc + 0][lr] = bv.x; Bs[lc + 1][lr] = bv.y;
        Bs[lc + 2][lr] = bv.z; Bs[lc + 3][lr] = bv.w;
        __syncthreads();
#pragma unroll
        for (int kk = 0; kk < 8; kk++) {
            float a[8], b[8];
            *(float4*)(a)     = *(const float4*)&As[kk][ty * 8];
            *(float4*)(a + 4) = *(const float4*)&As[kk][ty * 8 + 4];
            *(float4*)(b)     = *(const float4*)&Bs[kk][tx * 8];
            *(float4*)(b + 4) = *(const float4*)&Bs[kk][tx * 8 + 4];
#pragma unroll
            for (int i = 0; i < 8; i++)
#pragma unroll
                for (int j = 0; j < 8; j++)
                    acc[i][j] = fmaf(a[i], b[j], acc[i][j]);
        }
        __syncthreads();
    }

#pragma unroll
    for (int i = 0; i < 8; i++) {
        int row = bm + ty * 8 + i;
#pragma unroll
        for (int j = 0; j < 8; j += 4) {
            int col = bn + tx * 8 + j;
            float4 v = make_float4(acc[i][j], acc[i][j + 1],
                                   acc[i][j + 2], acc[i][j + 3]);
            if (EPI == 1) {
                v.x = softplus_f(v.x + bias[col + 0]);
                v.y = softplus_f(v.y + bias[col + 1]);
                v.z = softplus_f(v.z + bias[col + 2]);
                v.w = softplus_f(v.w + bias[col + 3]);
            } else if (EPI == 2) {
                v.x += bias[col + 0]; v.y += bias[col + 1];
                v.z += bias[col + 2]; v.w += bias[col + 3];
            }
            *(float4*)&Out[(size_t)row * N + col] = v;
        }
    }
}

// ---------------- fused bc-GEMM + SSM state update -------------------------
// bc[b, n] = x[b,:] . bc_w[n,:],  n = d*32 + (0..15 = B, 16..31 = C)
// Block tile: 128 batch rows x 128 bc cols (= 4 d-channels).
// After GEMM, stage the tile through SMEM (two 64-row passes) and run the
// elementwise SSM update: h_new = exp(dt*A)*h + dt*B*u ; y = sum(h_new*C)+D*u
// -> writes h_new to output, silu(y) to g_z.
__global__ void __launch_bounds__(256, 2)
mamba_core(const float* __restrict__ X, const float* __restrict__ Wbc,
           const float* __restrict__ H, const float* __restrict__ Dp,
           float* __restrict__ Hout)
{
    __shared__ __align__(16) float smem[64 * 129];   // 33 KB; reused as As/Bs then stage
    float (*As)[128] = (float(*)[128])smem;
    float (*Bs)[128] = (float(*)[128])(smem + 8 * 128);

    const int tid = threadIdx.x;
    const int tx  = tid & 15;
    const int ty  = tid >> 4;
    const int bm  = blockIdx.y * 128;
    const int bn  = blockIdx.x * 128;

    float acc[8][8];
#pragma unroll
    for (int i = 0; i < 8; i++)
#pragma unroll
        for (int j = 0; j < 8; j++) acc[i][j] = 0.f;

    const int lr = tid >> 1;
    const int lc = (tid & 1) * 4;
    const float* Ap = X   + (size_t)(bm + lr) * DM + lc;
    const float* Wp = Wbc + (size_t)(bn + lr) * DM + lc;

    for (int kt = 0; kt < DM; kt += 8) {
        float4 av = *(const float4*)(Ap + kt);
        float4 bv = *(const float4*)(Wp + kt);
        As[lc + 0][lr] = av.x; As[lc + 1][lr] = av.y;
        As[lc + 2][lr] = av.z; As[lc + 3][lr] = av.w;
        Bs[lc + 0][lr] = bv.x; Bs[lc + 1][lr] = bv.y;
        Bs[lc + 2][lr] = bv.z; Bs[lc + 3][lr] = bv.w;
        __syncthreads();
#pragma unroll
        for (int kk = 0; kk < 8; kk++) {
            float a[8], b[8];
            *(float4*)(a)     = *(const float4*)&As[kk][ty * 8];
            *(float4*)(a + 4) = *(const float4*)&As[kk][ty * 8 + 4];
            *(float4*)(b)     = *(const float4*)&Bs[kk][tx * 8];
            *(float4*)(b + 4) = *(const float4*)&Bs[kk][tx * 8 + 4];
#pragma unroll
            for (int i = 0; i < 8; i++)
#pragma unroll
                for (int j = 0; j < 8; j++)
                    acc[i][j] = fmaf(a[i], b[j], acc[i][j]);
        }
        __syncthreads();
    }

    // ---- fused epilogue: two passes of 64 batch rows ----
    float* stage = smem;                   // [64][129], row-padded (conflict-free)
    const int b  = tid & 63;
    const int dl = tid >> 6;               // 0..3 local d-channel
    const int dg = blockIdx.x * 4 + dl;    // global d index

#pragma unroll 1
    for (int p = 0; p < 2; p++) {
        __syncthreads();
        if ((ty >> 3) == p) {              // threads holding rows [p*64, p*64+64)
            int rb = (ty & 7) * 8;
#pragma unroll
            for (int i = 0; i < 8; i++)
#pragma unroll
                for (int j = 0; j < 8; j++)
                    stage[(rb + i) * 129 + tx * 8 + j] = acc[i][j];
        }
        __syncthreads();

        const int bg = bm + p * 64 + b;    // global batch row
        const float u  = g_u [(size_t)bg * DM + dg];
        const float dt = g_dt[(size_t)bg * DM + dg];
        const float dc = Dp[dg];
        const float4* hrow = (const float4*)(H    + ((size_t)bg * DM + dg) * DS);
        float4*       hout = (float4*)      (Hout + ((size_t)bg * DM + dg) * DS);
        const float*  srow = stage + b * 129 + dl * 32;

        float y = 0.f;
#pragma unroll
        for (int q = 0; q < 4; q++) {
            float4 hv = hrow[q];
            float hvv[4] = {hv.x, hv.y, hv.z, hv.w};
            float hnv[4];
#pragma unroll
            for (int r = 0; r < 4; r++) {
                int s = q * 4 + r;
                float a  = g_An[dg * DS + s];
                float Bv = srow[s];
                float Cv = srow[16 + s];
                float hn = __expf(dt * a) * hvv[r] + dt * Bv * u;
                hnv[r] = hn;
                y = fmaf(hn, Cv, y);
            }
            hout[q] = make_float4(hnv[0], hnv[1], hnv[2], hnv[3]);
        }
        y = fmaf(dc, u, y);
        g_z[(size_t)bg * DM + dg] = y / (1.f + __expf(-y));   // silu
    }
}

// ---------------- launch ----------------------------------------------------
extern "C" void kernel_launch(void* const* d_in, const int* in_sizes, int n_in,
                              void* d_out, int out_size)
{
    const float* x     = (const float*)d_in[0];
    const float* h     = (const float*)d_in[1];
    const float* in_w  = (const float*)d_in[2];
    const float* dt_w  = (const float*)d_in[3];
    const float* dt_b  = (const float*)d_in[4];
    const float* bc_w  = (const float*)d_in[5];
    const float* A_log = (const float*)d_in[6];
    const float* Dp    = (const float*)d_in[7];
    const float* out_w = (const float*)d_in[8];
    const float* out_b = (const float*)d_in[9];

    float* out  = (float*)d_out;                 // [4096, 1024]
    float* hout = out + (size_t)NB * DM;         // [4096, 1024, 16]

    float *p_u, *p_dt, *p_z;
    cudaGetSymbolAddress((void**)&p_u,  g_u);
    cudaGetSymbolAddress((void**)&p_dt, g_dt);
    cudaGetSymbolAddress((void**)&p_z,  g_z);

    // A = -exp(A_log)
    prep_A<<<(DM * DS + 255) / 256, 256>>>(A_log);

    // u = x @ in_proj_w.T ; delta = softplus(x @ dt_proj_w.T + b)
    dim3 gsq(DM / 128, NB / 128);                // (8, 32)
    sgemm128<0><<<gsq, 256>>>(x, in_w, nullptr, p_u,  DM, DM);
    sgemm128<1><<<gsq, 256>>>(x, dt_w, dt_b,    p_dt, DM, DM);

    // fused bc GEMM + SSM update -> h_new (output) + silu(y) (g_z)
    dim3 gbc(NBC / 128, NB / 128);               // (256, 32)
    mamba_core<<<gbc, 256>>>(x, bc_w, h, Dp, hout);

    // out = silu(y) @ out_proj_w.T + out_proj_b
    sgemm128<2><<<gsq, 256>>>(p_z, out_w, out_b, out, DM, DM);
}

// round 6
// speedup vs baseline: 3.0359x; 3.0359x over previous
#include <cuda_runtime.h>
#include <cstdint>
#include <math.h>

#define DM 1024
#define DS 16
#define NB 4096
#define NBC 32768

#define BM 128
#define BN 128
#define BK 32
#define NSTG 3
#define NTHREADS 256
#define STAGE_BYTES (2 * BM * BK * 4)     // A tile 16KB + B tile 16KB
#define SMEM_BYTES (NSTG * STAGE_BYTES)   // 98304

// ---------------- scratch (device globals) ---------------------------------
__device__ float g_xr [NB * DM];
__device__ float g_w1 [DM * DM];
__device__ float g_w2 [DM * DM];
__device__ float g_wo [DM * DM];
__device__ float g_wbc[NBC * DM];
__device__ float g_u  [NB * DM];
__device__ float g_dt [NB * DM];
__device__ float g_z  [NB * DM];
__device__ float g_An [DM * DS];

// ---------------- helpers ---------------------------------------------------
__device__ __forceinline__ uint32_t smem_u32(const void* p) {
    uint32_t a;
    asm("{ .reg .u64 t; cvta.to.shared.u64 t, %1; cvt.u32.u64 %0, t; }" : "=r"(a) : "l"(p));
    return a;
}
__device__ __forceinline__ void cpa16(uint32_t s, const void* g) {
    asm volatile("cp.async.cg.shared.global [%0], [%1], 16;" :: "r"(s), "l"(g));
}
__device__ __forceinline__ float tf32_rn(float v) {
    uint32_t o;
    asm("cvt.rna.tf32.f32 %0, %1;" : "=r"(o) : "f"(v));
    return __uint_as_float(o);
}
__device__ __forceinline__ float softplus_f(float x) {
    return x > 20.f ? x : log1pf(__expf(x));
}
#define LDSB32(v, a) asm volatile("ld.shared.b32 %0, [%1];" : "=r"(v) : "r"(a))

__device__ __forceinline__ void mma8(float* d, uint32_t a0, uint32_t a1,
                                     uint32_t a2, uint32_t a3,
                                     uint32_t b0, uint32_t b1) {
    asm volatile(
        "mma.sync.aligned.m16n8k8.row.col.f32.tf32.tf32.f32 "
        "{%0,%1,%2,%3}, {%4,%5,%6,%7}, {%8,%9}, {%0,%1,%2,%3};"
        : "+f"(d[0]), "+f"(d[1]), "+f"(d[2]), "+f"(d[3])
        : "r"(a0), "r"(a1), "r"(a2), "r"(a3), "r"(b0), "r"(b1));
}

// ---------------- gmem -> smem stage (swizzled) -----------------------------
// smem layout per operand: [BK/8=4][rows=128][8 floats], kc index XOR (row&4)
// -> every fragment LDS hits 32 distinct banks.
__device__ __forceinline__ void stage_load(const float* __restrict__ A,
                                           const float* __restrict__ W, int K,
                                           int bm, int bn, int chunk,
                                           uint32_t sbase, int tid) {
    const int kt = chunk * BK;
#pragma unroll
    for (int i = 0; i < 4; i++) {
        int id = tid + i * NTHREADS;           // 0..1023
        int row = id >> 3, ck = id & 7, ks = ck >> 1, kb = (ck & 1) * 4;
        cpa16(sbase + (ks * 128 + row) * 32 + ((kb ^ (row & 4)) << 2),
              A + (size_t)(bm + row) * K + kt + ks * 8 + kb);
    }
#pragma unroll
    for (int i = 0; i < 4; i++) {
        int id = tid + i * NTHREADS;
        int row = id >> 3, ck = id & 7, ks = ck >> 1, kb = (ck & 1) * 4;
        cpa16(sbase + BM * BK * 4 + (ks * 128 + row) * 32 + ((kb ^ (row & 4)) << 2),
              W + (size_t)(bn + row) * K + kt + ks * 8 + kb);
    }
    asm volatile("cp.async.commit_group;" ::: "memory");
}

// ---------------- pipelined tf32 mma mainloop -------------------------------
// Warp grid 2(M) x 4(N): warp tile 64x32. acc[mt][nt][4] = m16n8 fragments.
__device__ __forceinline__ void gemm_mainloop(const float* __restrict__ A,
                                              const float* __restrict__ W, int K,
                                              int bm, int bn, uint32_t smem_base,
                                              float acc[4][4][4]) {
    const int tid  = threadIdx.x;
    const int lane = tid & 31, wid = tid >> 5;
    const int wm = wid >> 2, wn = wid & 3;
    const int q = lane >> 2, c = lane & 3;
    const uint32_t c0 = (uint32_t)((c ^ (q & 4)) << 2);   // kc byte offset
    const uint32_t c1 = c0 ^ 16;

#pragma unroll
    for (int mt = 0; mt < 4; mt++)
#pragma unroll
        for (int nt = 0; nt < 4; nt++)
#pragma unroll
            for (int r = 0; r < 4; r++) acc[mt][nt][r] = 0.f;

    const int nch = K / BK;
#pragma unroll 1
    for (int s = 0; s < NSTG - 1; s++)
        stage_load(A, W, K, bm, bn, s, smem_base + s * STAGE_BYTES, tid);

#pragma unroll 1
    for (int i = 0; i < nch; i++) {
        asm volatile("cp.async.wait_group %0;" :: "n"(NSTG - 2) : "memory");
        __syncthreads();
        const int nx = i + NSTG - 1;
        if (nx < nch)
            stage_load(A, W, K, bm, bn, nx, smem_base + (nx % NSTG) * STAGE_BYTES, tid);

        const uint32_t st = smem_base + (i % NSTG) * STAGE_BYTES;
        const uint32_t aW = st + (wm * 64 + q) * 32;
        const uint32_t bW = st + BM * BK * 4 + (wn * 32 + q) * 32;
#pragma unroll
        for (int ks = 0; ks < 4; ks++) {
            uint32_t a[4][4], b[4][2];
#pragma unroll
            for (int mt = 0; mt < 4; mt++) {
                const uint32_t r0 = aW + ks * 4096 + mt * 16 * 32;
                LDSB32(a[mt][0], r0 + c0);
                LDSB32(a[mt][1], r0 + 256 + c0);
                LDSB32(a[mt][2], r0 + c1);
                LDSB32(a[mt][3], r0 + 256 + c1);
            }
#pragma unroll
            for (int nt = 0; nt < 4; nt++) {
                const uint32_t r0 = bW + ks * 4096 + nt * 8 * 32;
                LDSB32(b[nt][0], r0 + c0);
                LDSB32(b[nt][1], r0 + c1);
            }
#pragma unroll
            for (int mt = 0; mt < 4; mt++)
#pragma unroll
                for (int nt = 0; nt < 4; nt++)
                    mma8(acc[mt][nt], a[mt][0], a[mt][1], a[mt][2], a[mt][3],
                         b[nt][0], b[nt][1]);
        }
    }
}

// ---------------- generic tf32 GEMM: Out[M,N] = A @ W^T ---------------------
// EPI: 0=none, 1=softplus(v+bias), 2=v+bias
template <int EPI>
__global__ void __launch_bounds__(NTHREADS, 2)
gemm_tc(const float* __restrict__ A, const float* __restrict__ W,
        const float* __restrict__ bias, float* __restrict__ Out, int N, int K)
{
    extern __shared__ __align__(128) char smem[];
    const int bm = blockIdx.x * BM, bn = blockIdx.y * BN;
    float acc[4][4][4];
    gemm_mainloop(A, W, K, bm, bn, smem_u32(smem), acc);

    const int lane = threadIdx.x & 31, wid = threadIdx.x >> 5;
    const int wm = wid >> 2, wn = wid & 3;
    const int q = lane >> 2, c = lane & 3;

#pragma unroll
    for (int mt = 0; mt < 4; mt++) {
        const int row0 = bm + wm * 64 + mt * 16 + q;
#pragma unroll
        for (int nt = 0; nt < 4; nt++) {
            const int col = bn + wn * 32 + nt * 8 + 2 * c;
            float2 v0 = make_float2(acc[mt][nt][0], acc[mt][nt][1]);
            float2 v1 = make_float2(acc[mt][nt][2], acc[mt][nt][3]);
            if (EPI == 1) {
                const float2 b2 = *(const float2*)(bias + col);
                v0.x = softplus_f(v0.x + b2.x); v0.y = softplus_f(v0.y + b2.y);
                v1.x = softplus_f(v1.x + b2.x); v1.y = softplus_f(v1.y + b2.y);
            } else if (EPI == 2) {
                const float2 b2 = *(const float2*)(bias + col);
                v0.x += b2.x; v0.y += b2.y; v1.x += b2.x; v1.y += b2.y;
            }
            *(float2*)(Out + (size_t)row0 * N + col)       = v0;
            *(float2*)(Out + (size_t)(row0 + 8) * N + col) = v1;
        }
    }
}

// ---------------- fused bc GEMM + SSM state update --------------------------
// Each warp's 32 N-cols = exactly one d-channel's [B(16)|C(16)].
// Lane c owns s in {2c, 2c+1, 8+2c, 8+2c+1}; quad shfl-reduces y.
__global__ void __launch_bounds__(NTHREADS, 2)
mamba_tc(const float* __restrict__ A, const float* __restrict__ W,
         const float* __restrict__ H, const float* __restrict__ Dp,
         float* __restrict__ Hout)
{
    extern __shared__ __align__(128) char smem[];
    const int bm = blockIdx.x * BM, bn = blockIdx.y * BN;
    float acc[4][4][4];
    gemm_mainloop(A, W, DM, bm, bn, smem_u32(smem), acc);

    const int lane = threadIdx.x & 31, wid = threadIdx.x >> 5;
    const int wm = wid >> 2, wn = wid & 3;
    const int q = lane >> 2, c = lane & 3;
    const int dg = (bn >> 5) + wn;           // this warp's d-channel
    const int s0 = 2 * c;

    float An0 = g_An[dg * DS + s0],     An1 = g_An[dg * DS + s0 + 1];
    float An2 = g_An[dg * DS + s0 + 8], An3 = g_An[dg * DS + s0 + 9];
    const float dc = Dp[dg];

#pragma unroll
    for (int mt = 0; mt < 4; mt++) {
#pragma unroll
        for (int hf = 0; hf < 2; hf++) {
            const int bg = bm + wm * 64 + mt * 16 + q + 8 * hf;
            const float u  = g_u [(size_t)bg * DM + dg];
            const float dt = g_dt[(size_t)bg * DM + dg];
            const float Bv0 = acc[mt][0][2 * hf],  Bv1 = acc[mt][0][2 * hf + 1];
            const float Bv2 = acc[mt][1][2 * hf],  Bv3 = acc[mt][1][2 * hf + 1];
            const float Cv0 = acc[mt][2][2 * hf],  Cv1 = acc[mt][2][2 * hf + 1];
            const float Cv2 = acc[mt][3][2 * hf],  Cv3 = acc[mt][3][2 * hf + 1];

            const float* hp = H + ((size_t)bg * DM + dg) * DS;
            const float2 ha = *(const float2*)(hp + s0);
            const float2 hb = *(const float2*)(hp + 8 + s0);

            const float du = dt * u;
            const float h0 = __expf(dt * An0) * ha.x + du * Bv0;
            const float h1 = __expf(dt * An1) * ha.y + du * Bv1;
            const float h2 = __expf(dt * An2) * hb.x + du * Bv2;
            const float h3 = __expf(dt * An3) * hb.y + du * Bv3;

            float* ho = Hout + ((size_t)bg * DM + dg) * DS;
            *(float2*)(ho + s0)     = make_float2(h0, h1);
            *(float2*)(ho + 8 + s0) = make_float2(h2, h3);

            float y = h0 * Cv0 + h1 * Cv1 + h2 * Cv2 + h3 * Cv3;
            y += __shfl_xor_sync(0xffffffffu, y, 1);
            y += __shfl_xor_sync(0xffffffffu, y, 2);
            if (c == 0) {
                y = fmaf(dc, u, y);
                const float z = y / (1.f + __expf(-y));
                g_z[(size_t)bg * DM + dg] = tf32_rn(z);
            }
        }
    }
}

// ---------------- prep kernels ----------------------------------------------
__global__ void prep_A(const float* __restrict__ A_log) {
    int i = blockIdx.x * 256 + threadIdx.x;
    if (i < DM * DS) g_An[i] = -__expf(A_log[i]);
}
__global__ void round_tf32_k(const float* __restrict__ src, float* __restrict__ dst, int n) {
    int i = (blockIdx.x * 256 + threadIdx.x) * 4;
    if (i < n) {
        float4 v = *(const float4*)(src + i);
        v.x = tf32_rn(v.x); v.y = tf32_rn(v.y);
        v.z = tf32_rn(v.z); v.w = tf32_rn(v.w);
        *(float4*)(dst + i) = v;
    }
}

// ---------------- launch -----------------------------------------------------
extern "C" void kernel_launch(void* const* d_in, const int* in_sizes, int n_in,
                              void* d_out, int out_size)
{
    const float* x     = (const float*)d_in[0];
    const float* h     = (const float*)d_in[1];
    const float* in_w  = (const float*)d_in[2];
    const float* dt_w  = (const float*)d_in[3];
    const float* dt_b  = (const float*)d_in[4];
    const float* bc_w  = (const float*)d_in[5];
    const float* A_log = (const float*)d_in[6];
    const float* Dp    = (const float*)d_in[7];
    const float* out_w = (const float*)d_in[8];
    const float* out_b = (const float*)d_in[9];

    float* out  = (float*)d_out;
    float* hout = out + (size_t)NB * DM;

    float *p_xr, *p_w1, *p_w2, *p_wo, *p_wbc, *p_u, *p_dt, *p_z;
    cudaGetSymbolAddress((void**)&p_xr,  g_xr);
    cudaGetSymbolAddress((void**)&p_w1,  g_w1);
    cudaGetSymbolAddress((void**)&p_w2,  g_w2);
    cudaGetSymbolAddress((void**)&p_wo,  g_wo);
    cudaGetSymbolAddress((void**)&p_wbc, g_wbc);
    cudaGetSymbolAddress((void**)&p_u,   g_u);
    cudaGetSymbolAddress((void**)&p_dt,  g_dt);
    cudaGetSymbolAddress((void**)&p_z,   g_z);

    cudaFuncSetAttribute(gemm_tc<0>, cudaFuncAttributeMaxDynamicSharedMemorySize, SMEM_BYTES);
    cudaFuncSetAttribute(gemm_tc<1>, cudaFuncAttributeMaxDynamicSharedMemorySize, SMEM_BYTES);
    cudaFuncSetAttribute(gemm_tc<2>, cudaFuncAttributeMaxDynamicSharedMemorySize, SMEM_BYTES);
    cudaFuncSetAttribute(mamba_tc,   cudaFuncAttributeMaxDynamicSharedMemorySize, SMEM_BYTES);

    prep_A<<<(DM * DS + 255) / 256, 256>>>(A_log);
    round_tf32_k<<<(NB * DM / 4 + 255) / 256, 256>>>(x,     p_xr,  NB * DM);
    round_tf32_k<<<(DM * DM / 4 + 255) / 256, 256>>>(in_w,  p_w1,  DM * DM);
    round_tf32_k<<<(DM * DM / 4 + 255) / 256, 256>>>(dt_w,  p_w2,  DM * DM);
    round_tf32_k<<<(DM * DM / 4 + 255) / 256, 256>>>(out_w, p_wo,  DM * DM);
    round_tf32_k<<<(NBC * DM / 4 + 255) / 256, 256>>>(bc_w, p_wbc, NBC * DM);

    dim3 gsq(NB / BM, DM / BN);          // (32, 8)
    gemm_tc<0><<<gsq, NTHREADS, SMEM_BYTES>>>(p_xr, p_w1, nullptr, p_u,  DM, DM);
    gemm_tc<1><<<gsq, NTHREADS, SMEM_BYTES>>>(p_xr, p_w2, dt_b,    p_dt, DM, DM);

    dim3 gbc(NB / BM, NBC / BN);         // (32, 256)
    mamba_tc<<<gbc, NTHREADS, SMEM_BYTES>>>(p_xr, p_wbc, h, Dp, hout);

    gemm_tc<2><<<gsq, NTHREADS, SMEM_BYTES>>>(p_z, p_wo, out_b, out, DM, DM);
}